// round 2
// baseline (speedup 1.0000x reference)
#include <cuda_runtime.h>
#include <math.h>
#include <float.h>

#define BATCH  2
#define SEQ    2048
#define DMODEL 1024
#define NHEAD  16
#define DHEAD  64
#define TOPK   32

// ---------------- device scratch ----------------
__device__ float g_q[(size_t)BATCH * SEQ * DMODEL];
__device__ float g_k[(size_t)BATCH * SEQ * DMODEL];
__device__ float g_v[(size_t)BATCH * SEQ * DMODEL];
__device__ float g_ctx[(size_t)BATCH * SEQ * DMODEL];
__device__ float g_s[(size_t)BATCH * NHEAD * SEQ * SEQ];  // 536 MB score scratch

// =======================================================================================
// ACCURATE fp32 NT GEMM: C[M,N] = alpha * A[M,K]*W[N,K]^T (+bias)
// Short accumulation chains: per-thread partial p over 64-k chunks, folded into acc.
// 512 threads, 128x128 block tile, 4x8 microtile. Used for Q-proj, K-proj, scores
// (everything whose rounding feeds the top-k selection).
// =======================================================================================
template<int KTOT, bool HAS_BIAS>
__device__ __forceinline__ void gemm_nt_accurate(
    float* __restrict__ C, const float* __restrict__ A,
    const float* __restrict__ W, const float* __restrict__ bias,
    int lda, int ldb, int ldc, float alpha)
{
    __shared__ float As[16][132];
    __shared__ float Ws[16][132];
    const int tid = threadIdx.x;          // 0..511
    const int m0 = blockIdx.y * 128;
    const int n0 = blockIdx.x * 128;
    const int tr = tid >> 4;              // 0..31 -> rows tr*4..tr*4+3
    const int tc = tid & 15;              // 0..15 -> cols tc*8..tc*8+7
    const int r  = tid >> 2;              // 0..127 loader row
    const int c0 = (tid & 3) << 2;        // loader k-offset

    float acc[4][8];
#pragma unroll
    for (int i = 0; i < 4; i++)
#pragma unroll
        for (int j = 0; j < 8; j++) acc[i][j] = 0.f;

    constexpr int CHUNKS = KTOT / 64;     // 64-k chunk -> short inner chain
#pragma unroll 1
    for (int ch = 0; ch < CHUNKS; ch++) {
        float p[4][8];
#pragma unroll
        for (int t = 0; t < 4; t++) {
            const int k0 = ch * 64 + t * 16;
            float4 av = *(const float4*)(A + (size_t)(m0 + r) * lda + k0 + c0);
            As[c0 + 0][r] = av.x; As[c0 + 1][r] = av.y;
            As[c0 + 2][r] = av.z; As[c0 + 3][r] = av.w;
            float4 wv = *(const float4*)(W + (size_t)(n0 + r) * ldb + k0 + c0);
            Ws[c0 + 0][r] = wv.x; Ws[c0 + 1][r] = wv.y;
            Ws[c0 + 2][r] = wv.z; Ws[c0 + 3][r] = wv.w;
            __syncthreads();
#pragma unroll
            for (int k = 0; k < 16; k++) {
                float a[4], w[8];
                *(float4*)(a)     = *(const float4*)&As[k][tr * 4];
                *(float4*)(w)     = *(const float4*)&Ws[k][tc * 8];
                *(float4*)(w + 4) = *(const float4*)&Ws[k][tc * 8 + 4];
#pragma unroll
                for (int i = 0; i < 4; i++)
#pragma unroll
                    for (int j = 0; j < 8; j++) {
                        if (t == 0 && k == 0) p[i][j] = a[i] * w[j];
                        else                  p[i][j] += a[i] * w[j];
                    }
            }
            __syncthreads();
        }
#pragma unroll
        for (int i = 0; i < 4; i++)
#pragma unroll
            for (int j = 0; j < 8; j++) acc[i][j] += p[i][j];
    }

    float bb[8];
#pragma unroll
    for (int j = 0; j < 8; j++) bb[j] = HAS_BIAS ? bias[n0 + tc * 8 + j] : 0.f;
#pragma unroll
    for (int i = 0; i < 4; i++) {
        float4 o0, o1;
        o0.x = acc[i][0] * alpha + bb[0]; o0.y = acc[i][1] * alpha + bb[1];
        o0.z = acc[i][2] * alpha + bb[2]; o0.w = acc[i][3] * alpha + bb[3];
        o1.x = acc[i][4] * alpha + bb[4]; o1.y = acc[i][5] * alpha + bb[5];
        o1.z = acc[i][6] * alpha + bb[6]; o1.w = acc[i][7] * alpha + bb[7];
        float* crow = C + (size_t)(m0 + tr * 4 + i) * ldc + n0 + tc * 8;
        *(float4*)crow       = o0;
        *(float4*)(crow + 4) = o1;
    }
}

__global__ __launch_bounds__(512, 1) void qk_proj_kernel(
    int which, const float* __restrict__ A,
    const float* __restrict__ W, const float* __restrict__ bias)
{
    float* C = (which == 0) ? g_q : g_k;
    gemm_nt_accurate<1024, true>(C, A, W, bias, 1024, 1024, 1024, 1.0f);
}

__global__ __launch_bounds__(512, 1) void scores_gemm_kernel()
{
    const int z = blockIdx.z;        // b*NHEAD + h
    const int b = z >> 4;
    const int h = z & 15;
    const float* Ab = g_q + (size_t)b * SEQ * DMODEL + h * DHEAD;
    const float* Bb = g_k + (size_t)b * SEQ * DMODEL + h * DHEAD;
    float* Cz = g_s + (size_t)z * SEQ * SEQ;
    gemm_nt_accurate<64, false>(Cz, Ab, Bb, nullptr, DMODEL, DMODEL, SEQ, 0.125f);
}

// =======================================================================================
// FAST fp32 NT GEMM (256 thr, 8x8 microtile) — for V-proj and out-proj only
// (their rounding does not affect top-k selection).
// =======================================================================================
__device__ __forceinline__ void gemm_nt_1024_fast(
    float* __restrict__ C, const float* __restrict__ A,
    const float* __restrict__ W, const float* __restrict__ bias)
{
    __shared__ float As[16][132];
    __shared__ float Ws[16][132];
    const int tid = threadIdx.x;
    const int m0 = blockIdx.y * 128;
    const int n0 = blockIdx.x * 128;
    const int tr = tid >> 4;
    const int tc = tid & 15;
    float acc[8][8];
#pragma unroll
    for (int i = 0; i < 8; i++)
#pragma unroll
        for (int j = 0; j < 8; j++) acc[i][j] = 0.f;

    const int r0 = tid >> 2;
    const int c0 = (tid & 3) << 2;

    for (int k0 = 0; k0 < 1024; k0 += 16) {
#pragma unroll
        for (int t = 0; t < 2; t++) {
            int r = r0 + t * 64;
            float4 av = *(const float4*)(A + (size_t)(m0 + r) * 1024 + k0 + c0);
            As[c0 + 0][r] = av.x; As[c0 + 1][r] = av.y;
            As[c0 + 2][r] = av.z; As[c0 + 3][r] = av.w;
            float4 wv = *(const float4*)(W + (size_t)(n0 + r) * 1024 + k0 + c0);
            Ws[c0 + 0][r] = wv.x; Ws[c0 + 1][r] = wv.y;
            Ws[c0 + 2][r] = wv.z; Ws[c0 + 3][r] = wv.w;
        }
        __syncthreads();
#pragma unroll
        for (int k = 0; k < 16; k++) {
            float a[8], w[8];
            *(float4*)(a)     = *(const float4*)&As[k][tr * 8];
            *(float4*)(a + 4) = *(const float4*)&As[k][tr * 8 + 4];
            *(float4*)(w)     = *(const float4*)&Ws[k][tc * 8];
            *(float4*)(w + 4) = *(const float4*)&Ws[k][tc * 8 + 4];
#pragma unroll
            for (int i = 0; i < 8; i++)
#pragma unroll
                for (int j = 0; j < 8; j++)
                    acc[i][j] += a[i] * w[j];
        }
        __syncthreads();
    }

    float bb[8];
#pragma unroll
    for (int j = 0; j < 8; j++) bb[j] = bias[n0 + tc * 8 + j];
#pragma unroll
    for (int i = 0; i < 8; i++) {
        float4 o0, o1;
        o0.x = acc[i][0] + bb[0]; o0.y = acc[i][1] + bb[1];
        o0.z = acc[i][2] + bb[2]; o0.w = acc[i][3] + bb[3];
        o1.x = acc[i][4] + bb[4]; o1.y = acc[i][5] + bb[5];
        o1.z = acc[i][6] + bb[6]; o1.w = acc[i][7] + bb[7];
        float* crow = C + (size_t)(m0 + tr * 8 + i) * 1024 + n0 + tc * 8;
        *(float4*)crow       = o0;
        *(float4*)(crow + 4) = o1;
    }
}

__global__ __launch_bounds__(256, 2) void v_proj_kernel(
    const float* __restrict__ A, const float* __restrict__ W, const float* __restrict__ bias)
{
    gemm_nt_1024_fast(g_v, A, W, bias);
}

__global__ __launch_bounds__(256, 2) void out_gemm_kernel(
    float* __restrict__ C, const float* __restrict__ W, const float* __restrict__ bias)
{
    gemm_nt_1024_fast(C, g_ctx, W, bias);
}

// ---------------- top-k(32) + softmax + V gather; one warp per (b,q,h) row ----------------
__global__ __launch_bounds__(128) void topk_attn_kernel(const int* __restrict__ mask)
{
    __shared__ float sv[4][SEQ];
    __shared__ float selv[4][TOPK];
    __shared__ int   seli[4][TOPK];

    const int warp = threadIdx.x >> 5;
    const int lane = threadIdx.x & 31;
    const int rid = blockIdx.x * 4 + warp;     // (b*SEQ + q)*NHEAD + h
    const int h  = rid & 15;
    const int bq = rid >> 4;
    const int q  = bq & (SEQ - 1);
    const int b  = bq >> 11;

    const float* srow = g_s + ((size_t)(b * NHEAD + h) * SEQ + q) * SEQ;
    const int*   mrow = mask + ((size_t)b * SEQ + q) * SEQ;
    float* svw = sv[warp];

    for (int j = lane; j < SEQ; j += 32) {
        float v = srow[j];
        if (mrow[j] == 0) v = -1e9f;
        svw[j] = v;
    }
    __syncwarp();

    // per-lane cached max over contiguous segment [lane*64, lane*64+64)
    float mv = -INFINITY; int mi = 0x7fffffff;
    const int base = lane << 6;
#pragma unroll 8
    for (int j0 = 0; j0 < 64; j0++) {
        int j = base + ((j0 + lane) & 63);
        float v = svw[j];
        if (v > mv || (v == mv && j < mi)) { mv = v; mi = j; }
    }

    for (int it = 0; it < TOPK; it++) {
        float bv = mv; int bi = mi;
#pragma unroll
        for (int off = 16; off; off >>= 1) {
            float ov = __shfl_xor_sync(0xffffffffu, bv, off);
            int   oi = __shfl_xor_sync(0xffffffffu, bi, off);
            if (ov > bv || (ov == bv && oi < bi)) { bv = ov; bi = oi; }
        }
        if (lane == 0) {
            selv[warp][it] = bv;
            seli[warp][it] = bi;
            svw[bi] = -INFINITY;
        }
        const int owner = bi >> 6;
        __syncwarp();
        const int i0 = (owner << 6) + (lane << 1);
        float2 c = *(const float2*)&svw[i0];
        float nv; int ni;
        if (c.x >= c.y) { nv = c.x; ni = i0; } else { nv = c.y; ni = i0 + 1; }
#pragma unroll
        for (int off = 16; off; off >>= 1) {
            float ov = __shfl_xor_sync(0xffffffffu, nv, off);
            int   oi = __shfl_xor_sync(0xffffffffu, ni, off);
            if (ov > nv || (ov == nv && oi < ni)) { nv = ov; ni = oi; }
        }
        if (lane == owner) { mv = nv; mi = ni; }
    }
    __syncwarp();

    const float vsel = selv[warp][lane];
    const float vmax = selv[warp][0];
    float e = expf(vsel - vmax);
    float ssum = e;
#pragma unroll
    for (int off = 16; off; off >>= 1) ssum += __shfl_xor_sync(0xffffffffu, ssum, off);
    const float p = e / ssum;

    const float* vb = g_v + (size_t)b * SEQ * DMODEL + h * DHEAD;
    float acc0 = 0.f, acc1 = 0.f;
#pragma unroll 4
    for (int j = 0; j < TOPK; j++) {
        float pj = __shfl_sync(0xffffffffu, p, j);
        int idx = seli[warp][j];
        const float* vr = vb + (size_t)idx * DMODEL;
        acc0 += pj * vr[lane];
        acc1 += pj * vr[lane + 32];
    }
    float* crow = g_ctx + ((size_t)(b * SEQ + q)) * DMODEL + h * DHEAD;
    crow[lane]      = acc0;
    crow[lane + 32] = acc1;
}

// ---------------- launch ----------------
extern "C" void kernel_launch(void* const* d_in, const int* in_sizes, int n_in,
                              void* d_out, int out_size)
{
    const float* query = (const float*)d_in[0];
    const float* key   = (const float*)d_in[1];
    const float* value = (const float*)d_in[2];
    const float* Wq    = (const float*)d_in[3];
    const float* bq    = (const float*)d_in[4];
    const float* Wk    = (const float*)d_in[5];
    const float* bk    = (const float*)d_in[6];
    const float* Wv    = (const float*)d_in[7];
    const float* bv    = (const float*)d_in[8];
    const float* Wo    = (const float*)d_in[9];
    const float* bo    = (const float*)d_in[10];
    const int*   mask  = (const int*)d_in[11];
    (void)in_sizes; (void)n_in; (void)out_size;

    dim3 gp(DMODEL / 128, (BATCH * SEQ) / 128);        // (8, 32)
    qk_proj_kernel<<<gp, 512>>>(0, query, Wq, bq);
    qk_proj_kernel<<<gp, 512>>>(1, key,   Wk, bk);
    v_proj_kernel<<<gp, 256>>>(value, Wv, bv);

    dim3 gs(SEQ / 128, SEQ / 128, BATCH * NHEAD);      // (16, 16, 32)
    scores_gemm_kernel<<<gs, 512>>>();

    topk_attn_kernel<<<(BATCH * SEQ * NHEAD) / 4, 128>>>(mask);

    out_gemm_kernel<<<gp, 256>>>((float*)d_out, Wo, bo);
}